// round 10
// baseline (speedup 1.0000x reference)
#include <cuda_runtime.h>
#include <stdint.h>

#define NSTEP  1000
#define NELEM  45056     // 16*1*64*44
#define HW     2816      // 64*44
#define EPB    64        // elements per block
#define TPB    256       // warps 0-1 solver(+4 gens), 2-7 producers (7 gens)
#define NBLK   704       // 45056 / 64
#define CSTEP  50        // steps per chunk
#define NCHUNK 20        // 1000 / 50

// =================== compile-time schedule + folded keys ===================
struct alignas(16) F4 { float x, y, z, w; };
struct alignas(16) U4 { unsigned x, y, z, w; };   // {ks0, ks1, ks2, 0}

struct SchedData {
  F4 sc[NSTEP];     // {P, Q, C1, TCO}
  U4 key[NSTEP];    // {ks0, ks1, ks2, 0}
};

constexpr double csqrt(double x) {
  double r = (x > 1.0) ? x : 1.0;
  for (int i = 0; i < 48; i++) r = 0.5 * (r + x / r);
  return r;
}
constexpr unsigned crotl(unsigned v, int r) { return (v << r) | (v >> (32 - r)); }
constexpr void ctf_round(unsigned& x0, unsigned& x1, int r) {
  x0 += x1; x1 = crotl(x1, r); x1 ^= x0;
}
constexpr void cthreefry(unsigned ks0, unsigned ks1, unsigned x0, unsigned x1,
                         unsigned& o0, unsigned& o1) {
  const unsigned ks2 = ks0 ^ ks1 ^ 0x1BD11BDAu;
  x0 += ks0; x1 += ks1;
  ctf_round(x0,x1,13); ctf_round(x0,x1,15); ctf_round(x0,x1,26); ctf_round(x0,x1,6);
  x0 += ks1; x1 += ks2 + 1u;
  ctf_round(x0,x1,17); ctf_round(x0,x1,29); ctf_round(x0,x1,16); ctf_round(x0,x1,24);
  x0 += ks2; x1 += ks0 + 2u;
  ctf_round(x0,x1,13); ctf_round(x0,x1,15); ctf_round(x0,x1,26); ctf_round(x0,x1,6);
  x0 += ks0; x1 += ks1 + 3u;
  ctf_round(x0,x1,17); ctf_round(x0,x1,29); ctf_round(x0,x1,16); ctf_round(x0,x1,24);
  x0 += ks1; x1 += ks2 + 4u;
  ctf_round(x0,x1,13); ctf_round(x0,x1,15); ctf_round(x0,x1,26); ctf_round(x0,x1,6);
  o0 = x0 + ks2;
  o1 = x1 + ks0 + 5u;
}

constexpr SchedData make_sched() {
  SchedData s{};
  double alph[NSTEP + 1] = {};
  alph[0] = 1.0;
  {
    double prod = 1.0;
    const double bstep = (0.02 - 1e-4) / 999.0;
    for (int i = 0; i < NSTEP; i++) {
      double beta = (i == 999) ? 0.02 : (1e-4 + (double)i * bstep);
      prod *= (1.0 - beta);
      alph[i + 1] = prod;
    }
  }
  for (int k = 0; k < NSTEP; k++) {
    const int idx = 999 - k;
    const float at  = (float)alph[idx + 1];
    const float atn = (float)alph[idx];            // k==999 -> 1.0
    const float a1  = 1.0f - at / atn;
    const float c1  = 0.1f * (float)csqrt((double)(a1 * (1.0f - atn) / (1.0f - at)));
    float t2 = 1.0f - atn - c1 * c1; if (t2 < 0.0f) t2 = 0.0f;
    const float c2  = (float)csqrt((double)t2);
    const double s1 = csqrt(1.0 - (double)at);
    const double Qd = (double)c2 / s1;                               // coeff of sil_T
    const double Pd = (double)(float)csqrt((double)atn)
                    - Qd * (double)(float)csqrt((double)at);         // coeff of sil_0
    s.sc[k].x = (float)Pd; s.sc[k].y = (float)Qd; s.sc[k].z = c1;
    s.sc[k].w = (float)idx / 1000.0f;
    unsigned k0 = 0, k1 = 0;
    cthreefry(0u, 42u, 0u, (unsigned)idx, k0, k1);   // fold_in(key(42), idx)
    s.key[k].x = k0; s.key[k].y = k1;
    s.key[k].z = k0 ^ k1 ^ 0x1BD11BDAu;
    s.key[k].w = 0u;
  }
  return s;
}

__constant__ SchedData c_sched = make_sched();

// =================== 2-element interleaved threefry -> 2 normals ===================
// RS: SHF rotate (alu pipe).
// RM: rotate via IMAD.WIDE.U32 (fma pipe) — mul.wide.u32 by 2^r gives
//     {lo,hi} with disjoint bits, so rotl = lo|hi = lo^hi; fold the ^x0
//     into one 3-input LOP3. Inline PTX prevents frontend strength-reduction.
#define RS(RR)                                                 \
  _Pragma("unroll") for (int j = 0; j < 2; j++) {              \
    x0[j] += x1[j];                                            \
    x1[j] = __funnelshift_l(x1[j], x1[j], (RR)) ^ x0[j];       \
  }
#define RM(RR)                                                        \
  _Pragma("unroll") for (int j = 0; j < 2; j++) {                     \
    x0[j] += x1[j];                                                   \
    uint64_t p_;                                                      \
    asm("mul.wide.u32 %0, %1, %2;"                                    \
        : "=l"(p_) : "r"(x1[j]), "n"(1u << (RR)));                    \
    x1[j] = x0[j] ^ (uint32_t)p_ ^ (uint32_t)(p_ >> 32);              \
  }

__device__ __forceinline__ void gen2(U4 kk, uint32_t ctrA, uint32_t ctrB,
                                     float* out) {
  const uint32_t ks0 = kk.x, ks1 = kk.y, ks2 = kk.z;
  uint32_t x0[2], x1[2];
  x0[0] = ks0; x1[0] = ctrA + ks1;
  x0[1] = ks0; x1[1] = ctrB + ks1;
  // 13 RM (fma pipe) / 7 RS (alu pipe) for pipe balance
  RM(13) RS(15) RM(26) RS(6)
#pragma unroll
  for (int j = 0; j < 2; j++) { x0[j] += ks1; x1[j] += ks2 + 1u; }
  RM(17) RS(29) RM(16) RS(24)
#pragma unroll
  for (int j = 0; j < 2; j++) { x0[j] += ks2; x1[j] += ks0 + 2u; }
  RM(13) RS(15) RM(26) RS(6)
#pragma unroll
  for (int j = 0; j < 2; j++) { x0[j] += ks0; x1[j] += ks1 + 3u; }
  RM(17) RM(29) RM(16) RM(24)
#pragma unroll
  for (int j = 0; j < 2; j++) { x0[j] += ks1; x1[j] += ks2 + 4u; }
  RM(13) RM(15) RS(26) RM(6)

  float uu[2], ww[2];
#pragma unroll
  for (int j = 0; j < 2; j++) {
    const uint32_t bits = (x0[j] + ks2) ^ (x1[j] + ks0 + 5u);   // o0 ^ o1
    const float f = __uint_as_float((bits >> 9) | 0x3f800000u) - 1.0f;
    uu[j] = fmaf(f, 2.0f, -0.99999994f);
    ww[j] = -__logf(fmaf(-uu[j], uu[j], 1.0f));
  }
#pragma unroll
  for (int j = 0; j < 2; j++) {
    float w = ww[j], p;
    if (w < 5.0f) {  // XLA ErfInv32 (Giles)
      w -= 2.5f;
      p =             2.81022636e-08f;
      p = fmaf(p, w,  3.43273939e-07f);
      p = fmaf(p, w, -3.5233877e-06f);
      p = fmaf(p, w, -4.39150654e-06f);
      p = fmaf(p, w,  0.00021858087f);
      p = fmaf(p, w, -0.00125372503f);
      p = fmaf(p, w, -0.00417768164f);
      p = fmaf(p, w,  0.246640727f);
      p = fmaf(p, w,  1.50140941f);
    } else {
      w = sqrtf(w) - 3.0f;
      p =            -0.000200214257f;
      p = fmaf(p, w,  0.000100950558f);
      p = fmaf(p, w,  0.00134934322f);
      p = fmaf(p, w, -0.00367342844f);
      p = fmaf(p, w,  0.00573950773f);
      p = fmaf(p, w, -0.0076224613f);
      p = fmaf(p, w,  0.00943887047f);
      p = fmaf(p, w,  1.00167406f);
      p = fmaf(p, w,  2.83297682f);
    }
    out[j] = 1.41421356f * (p * uu[j]);
  }
}

__device__ __forceinline__ float tanh_fast(float x) {
  float y;
  asm("tanh.approx.f32 %0, %1;" : "=f"(y) : "f"(x));
  return y;
}

// =================== fused producer/consumer-in-block kernel ===================
__global__ void __launch_bounds__(TPB, 4) fused_all(
    const float* __restrict__ skes, const float* __restrict__ silT_g,
    const float* __restrict__ w_skes, const float* __restrict__ w_sil_p,
    const float* __restrict__ t_scale_p, float* __restrict__ preds)
{
  __shared__ float s_buf[2][CSTEP][EPB];

  const int tid  = threadIdx.x;
  const int lane = tid & 31;
  const int wid  = tid >> 5;            // 0..7
  const int base = blockIdx.x * EPB;
  const uint32_t ctrA = (uint32_t)(base + lane);
  const uint32_t ctrB = ctrA + 32u;

  // solver-only state (tid < EPB)
  float sil = 0.f, silT = 0.f, cond = 0.f, wsil = 0.f, tsc = 0.f;
  if (tid < EPB) {
    const int i  = base + tid;
    const int ns = i / HW;
    const int r  = i - ns * HW;
    const int n  = ns >> 3, sf = ns & 7;
    const float* bp = skes + (size_t)(n * 24 + sf) * HW + r;   // c stride = 8*HW
    cond = bp[0] * w_skes[0] + bp[8 * HW] * w_skes[1] + bp[16 * HW] * w_skes[2];
    silT = silT_g[i];
    wsil = *w_sil_p;
    tsc  = *t_scale_p;
    sil  = silT;
  }

  // ---- prologue: chunk 0 — warp w covers steps w, w+8, ... ----
  for (int s = wid; s < CSTEP; s += 8) {
    float o[2];
    gen2(c_sched.key[s], ctrA, ctrB, o);
    s_buf[0][s][lane]      = o[0];
    s_buf[0][s][lane + 32] = o[1];
  }
  __syncthreads();

  // ---- main loop: 20 chunks ----
  // quotas per chunk: solver warps 0-1 -> 4 gens each; producers 2-7 -> 7 each
  for (int g = 0; g < NCHUNK; g++) {
    const int cb = g & 1, nb = cb ^ 1;

    if (g < NCHUNK - 1) {
      const int kb = (g + 1) * CSTEP;
      if (wid >= 2) {
        const int sb = 8 + (wid - 2) * 7;       // steps [sb, sb+7)
#pragma unroll
        for (int jp = 0; jp < 7; jp++) {
          float o[2];
          gen2(c_sched.key[kb + sb + jp], ctrA, ctrB, o);
          s_buf[nb][sb + jp][lane]      = o[0];
          s_buf[nb][sb + jp][lane + 32] = o[1];
        }
      } else {
        const int sb = wid * 4;                 // steps [sb, sb+4)
#pragma unroll
        for (int jp = 0; jp < 4; jp++) {
          float o[2];
          gen2(c_sched.key[kb + sb + jp], ctrA, ctrB, o);
          s_buf[nb][sb + jp][lane]      = o[0];
          s_buf[nb][sb + jp][lane + 32] = o[1];
        }
      }
    }

    if (tid < EPB) {
      // consume current chunk: 50 sequential DDIM steps
      float* op = preds + (size_t)(g * CSTEP) * NELEM + base + tid;
#pragma unroll 5
      for (int u = 0; u < CSTEP; u++) {
        const F4 c = c_sched.sc[g * CSTEP + u];   // uniform -> const cache
        const float z  = fmaf(wsil, sil, fmaf(tsc, c.w, cond));
        const float s0 = tanh_fast(z);
        op[(size_t)u * NELEM] = s0;
        sil = fmaf(c.x, s0, fmaf(c.z, s_buf[cb][u][tid], c.y * silT));
      }
    }
    __syncthreads();
  }
}

// =================== launch ===================
extern "C" void kernel_launch(void* const* d_in, const int* in_sizes, int n_in,
                              void* d_out, int out_size) {
  const float* skes    = (const float*)d_in[0];  // (2,3,8,64,44)
  const float* sil_T   = (const float*)d_in[1];  // (16,1,64,44)
  const float* w_skes  = (const float*)d_in[2];  // (3,)
  const float* w_sil   = (const float*)d_in[3];  // ()
  const float* t_scale = (const float*)d_in[4];  // ()
  float* preds = (float*)d_out;                  // (1000,16,1,64,44)

  fused_all<<<NBLK, TPB>>>(skes, sil_T, w_skes, w_sil, t_scale, preds);
}

// round 11
// speedup vs baseline: 1.1564x; 1.1564x over previous
#include <cuda_runtime.h>
#include <stdint.h>

#define NSTEP  1000
#define NELEM  45056     // 16*1*64*44
#define HW     2816      // 64*44
#define EPB    64        // elements per block
#define TPB    256       // warps 0-1 solver(+4 gens), 2-7 producers (7 gens)
#define NBLK   704       // 45056 / 64
#define CSTEP  50        // steps per chunk
#define NCHUNK 20        // 1000 / 50

// =================== compile-time schedule + folded keys ===================
struct alignas(16) F4 { float x, y, z, w; };
struct alignas(16) U4 { unsigned x, y, z, w; };   // {ks0, ks1, ks2, 0}

struct SchedData {
  F4 sc[NSTEP];     // {P, Q, C1, TCO}
  U4 key[NSTEP];    // {ks0, ks1, ks2, 0}
};

constexpr double csqrt(double x) {
  double r = (x > 1.0) ? x : 1.0;
  for (int i = 0; i < 48; i++) r = 0.5 * (r + x / r);
  return r;
}
constexpr unsigned crotl(unsigned v, int r) { return (v << r) | (v >> (32 - r)); }
constexpr void ctf_round(unsigned& x0, unsigned& x1, int r) {
  x0 += x1; x1 = crotl(x1, r); x1 ^= x0;
}
constexpr void cthreefry(unsigned ks0, unsigned ks1, unsigned x0, unsigned x1,
                         unsigned& o0, unsigned& o1) {
  const unsigned ks2 = ks0 ^ ks1 ^ 0x1BD11BDAu;
  x0 += ks0; x1 += ks1;
  ctf_round(x0,x1,13); ctf_round(x0,x1,15); ctf_round(x0,x1,26); ctf_round(x0,x1,6);
  x0 += ks1; x1 += ks2 + 1u;
  ctf_round(x0,x1,17); ctf_round(x0,x1,29); ctf_round(x0,x1,16); ctf_round(x0,x1,24);
  x0 += ks2; x1 += ks0 + 2u;
  ctf_round(x0,x1,13); ctf_round(x0,x1,15); ctf_round(x0,x1,26); ctf_round(x0,x1,6);
  x0 += ks0; x1 += ks1 + 3u;
  ctf_round(x0,x1,17); ctf_round(x0,x1,29); ctf_round(x0,x1,16); ctf_round(x0,x1,24);
  x0 += ks1; x1 += ks2 + 4u;
  ctf_round(x0,x1,13); ctf_round(x0,x1,15); ctf_round(x0,x1,26); ctf_round(x0,x1,6);
  o0 = x0 + ks2;
  o1 = x1 + ks0 + 5u;
}

constexpr SchedData make_sched() {
  SchedData s{};
  double alph[NSTEP + 1] = {};
  alph[0] = 1.0;
  {
    double prod = 1.0;
    const double bstep = (0.02 - 1e-4) / 999.0;
    for (int i = 0; i < NSTEP; i++) {
      double beta = (i == 999) ? 0.02 : (1e-4 + (double)i * bstep);
      prod *= (1.0 - beta);
      alph[i + 1] = prod;
    }
  }
  for (int k = 0; k < NSTEP; k++) {
    const int idx = 999 - k;
    const float at  = (float)alph[idx + 1];
    const float atn = (float)alph[idx];            // k==999 -> 1.0
    const float a1  = 1.0f - at / atn;
    const float c1  = 0.1f * (float)csqrt((double)(a1 * (1.0f - atn) / (1.0f - at)));
    float t2 = 1.0f - atn - c1 * c1; if (t2 < 0.0f) t2 = 0.0f;
    const float c2  = (float)csqrt((double)t2);
    const double s1 = csqrt(1.0 - (double)at);
    const double Qd = (double)c2 / s1;                               // coeff of sil_T
    const double Pd = (double)(float)csqrt((double)atn)
                    - Qd * (double)(float)csqrt((double)at);         // coeff of sil_0
    s.sc[k].x = (float)Pd; s.sc[k].y = (float)Qd; s.sc[k].z = c1;
    s.sc[k].w = (float)idx / 1000.0f;
    unsigned k0 = 0, k1 = 0;
    cthreefry(0u, 42u, 0u, (unsigned)idx, k0, k1);   // fold_in(key(42), idx)
    s.key[k].x = k0; s.key[k].y = k1;
    s.key[k].z = k0 ^ k1 ^ 0x1BD11BDAu;
    s.key[k].w = 0u;
  }
  return s;
}

__constant__ SchedData c_sched = make_sched();

// ============ erfinv poly with sqrt(2) pre-folded into coefficients ============
__device__ __forceinline__ float erfinv_sqrt2_times(float u, float w) {
  float p;
  if (w < 5.0f) {
    w -= 2.5f;
    p =             3.97426473e-08f;
    p = fmaf(p, w,  4.85462767e-07f);
    p = fmaf(p, w, -4.98282941e-06f);
    p = fmaf(p, w, -6.21047292e-06f);
    p = fmaf(p, w,  3.09119798e-04f);
    p = fmaf(p, w, -1.77304226e-03f);
    p = fmaf(p, w, -5.90813969e-03f);
    p = fmaf(p, w,  3.48803866e-01f);
    p = fmaf(p, w,  2.12331426e+00f);
  } else {
    w = sqrtf(w) - 3.0f;
    p =            -2.83146474e-04f;
    p = fmaf(p, w,  1.42765667e-04f);
    p = fmaf(p, w,  1.90826894e-03f);
    p = fmaf(p, w, -5.19508745e-03f);
    p = fmaf(p, w,  8.11695397e-03f);
    p = fmaf(p, w, -1.07798600e-02f);
    p = fmaf(p, w,  1.33486509e-02f);
    p = fmaf(p, w,  1.41658103e+00f);
    p = fmaf(p, w,  4.00626600e+00f);
  }
  return p * u;
}

// =================== N-wide interleaved threefry -> N normals ===================
#define RN(RR, N)                                              \
  _Pragma("unroll") for (int j = 0; j < (N); j++) {            \
    x0[j] += x1[j];                                            \
    x1[j] = __funnelshift_l(x1[j], x1[j], (RR)) ^ x0[j];       \
  }

// 2 chains: one step key, elements ctrA/ctrB
__device__ __forceinline__ void gen2(U4 kk, uint32_t ctrA, uint32_t ctrB,
                                     float* out) {
  const uint32_t ks0 = kk.x, ks1 = kk.y, ks2 = kk.z;
  uint32_t x0[2], x1[2];
  x0[0] = ks0; x1[0] = ctrA + ks1;
  x0[1] = ks0; x1[1] = ctrB + ks1;
  RN(13,2) RN(15,2) RN(26,2) RN(6,2)
#pragma unroll
  for (int j = 0; j < 2; j++) { x0[j] += ks1; x1[j] += ks2 + 1u; }
  RN(17,2) RN(29,2) RN(16,2) RN(24,2)
#pragma unroll
  for (int j = 0; j < 2; j++) { x0[j] += ks2; x1[j] += ks0 + 2u; }
  RN(13,2) RN(15,2) RN(26,2) RN(6,2)
#pragma unroll
  for (int j = 0; j < 2; j++) { x0[j] += ks0; x1[j] += ks1 + 3u; }
  RN(17,2) RN(29,2) RN(16,2) RN(24,2)
#pragma unroll
  for (int j = 0; j < 2; j++) { x0[j] += ks1; x1[j] += ks2 + 4u; }
  RN(13,2) RN(15,2) RN(26,2) RN(6,2)
  float uu[2], ww[2];
#pragma unroll
  for (int j = 0; j < 2; j++) {
    const uint32_t bits = (x0[j] + ks2) ^ (x1[j] + ks0 + 5u);
    const float f = __uint_as_float((bits >> 9) | 0x3f800000u) - 1.0f;
    uu[j] = fmaf(f, 2.0f, -0.99999994f);
    ww[j] = -__logf(fmaf(-uu[j], uu[j], 1.0f));
  }
#pragma unroll
  for (int j = 0; j < 2; j++) out[j] = erfinv_sqrt2_times(uu[j], ww[j]);
}

// 4 chains: two step keys (ka, kb) x two elements (ctrA, ctrB)
// out[0]=stepA/elemA out[1]=stepA/elemB out[2]=stepB/elemA out[3]=stepB/elemB
__device__ __forceinline__ void gen4(U4 ka, U4 kb, uint32_t ctrA, uint32_t ctrB,
                                     float* out) {
  uint32_t k0[4], k1[4], k2[4], x0[4], x1[4];
#pragma unroll
  for (int j = 0; j < 4; j++) {
    const U4 kk = (j < 2) ? ka : kb;
    k0[j] = kk.x; k1[j] = kk.y; k2[j] = kk.z;
    x0[j] = k0[j];
    x1[j] = ((j & 1) ? ctrB : ctrA) + k1[j];
  }
  RN(13,4) RN(15,4) RN(26,4) RN(6,4)
#pragma unroll
  for (int j = 0; j < 4; j++) { x0[j] += k1[j]; x1[j] += k2[j] + 1u; }
  RN(17,4) RN(29,4) RN(16,4) RN(24,4)
#pragma unroll
  for (int j = 0; j < 4; j++) { x0[j] += k2[j]; x1[j] += k0[j] + 2u; }
  RN(13,4) RN(15,4) RN(26,4) RN(6,4)
#pragma unroll
  for (int j = 0; j < 4; j++) { x0[j] += k0[j]; x1[j] += k1[j] + 3u; }
  RN(17,4) RN(29,4) RN(16,4) RN(24,4)
#pragma unroll
  for (int j = 0; j < 4; j++) { x0[j] += k1[j]; x1[j] += k2[j] + 4u; }
  RN(13,4) RN(15,4) RN(26,4) RN(6,4)
  float uu[4], ww[4];
#pragma unroll
  for (int j = 0; j < 4; j++) {
    const uint32_t bits = (x0[j] + k2[j]) ^ (x1[j] + k0[j] + 5u);
    const float f = __uint_as_float((bits >> 9) | 0x3f800000u) - 1.0f;
    uu[j] = fmaf(f, 2.0f, -0.99999994f);
    ww[j] = -__logf(fmaf(-uu[j], uu[j], 1.0f));
  }
#pragma unroll
  for (int j = 0; j < 4; j++) out[j] = erfinv_sqrt2_times(uu[j], ww[j]);
}

__device__ __forceinline__ float tanh_fast(float x) {
  float y;
  asm("tanh.approx.f32 %0, %1;" : "=f"(y) : "f"(x));
  return y;
}

// =================== fused producer/consumer-in-block kernel ===================
__global__ void __launch_bounds__(TPB, 4) fused_all(
    const float* __restrict__ skes, const float* __restrict__ silT_g,
    const float* __restrict__ w_skes, const float* __restrict__ w_sil_p,
    const float* __restrict__ t_scale_p, float* __restrict__ preds)
{
  __shared__ float s_buf[2][CSTEP][EPB];

  const int tid  = threadIdx.x;
  const int lane = tid & 31;
  const int wid  = tid >> 5;            // 0..7
  const int base = blockIdx.x * EPB;
  const uint32_t ctrA = (uint32_t)(base + lane);
  const uint32_t ctrB = ctrA + 32u;

  // solver-only state (tid < EPB)
  float sil = 0.f, silT = 0.f, cond = 0.f, wsil = 0.f, tsc = 0.f;
  if (tid < EPB) {
    const int i  = base + tid;
    const int ns = i / HW;
    const int r  = i - ns * HW;
    const int n  = ns >> 3, sf = ns & 7;
    const float* bp = skes + (size_t)(n * 24 + sf) * HW + r;   // c stride = 8*HW
    cond = bp[0] * w_skes[0] + bp[8 * HW] * w_skes[1] + bp[16 * HW] * w_skes[2];
    silT = silT_g[i];
    wsil = *w_sil_p;
    tsc  = *t_scale_p;
    sil  = silT;
  }

  // ---- prologue: chunk 0 — warp w covers step pairs (2w,2w+1), +16, ... ----
  for (int s = 2 * wid; s < 48; s += 16) {
    float o[4];
    gen4(c_sched.key[s], c_sched.key[s + 1], ctrA, ctrB, o);
    s_buf[0][s][lane]          = o[0];
    s_buf[0][s][lane + 32]     = o[1];
    s_buf[0][s + 1][lane]      = o[2];
    s_buf[0][s + 1][lane + 32] = o[3];
  }
  if (wid < 2) {  // steps 48, 49
    float o[2];
    gen2(c_sched.key[48 + wid], ctrA, ctrB, o);
    s_buf[0][48 + wid][lane]      = o[0];
    s_buf[0][48 + wid][lane + 32] = o[1];
  }
  __syncthreads();

  // ---- main loop: 20 chunks ----
  // quotas per chunk: solver warps 0-1 -> 4 steps (2x gen4); producers -> 7 (3x gen4 + gen2)
  for (int g = 0; g < NCHUNK; g++) {
    const int cb = g & 1, nb = cb ^ 1;

    if (g < NCHUNK - 1) {
      const int kb = (g + 1) * CSTEP;
      if (wid >= 2) {
        const int sb = 8 + (wid - 2) * 7;       // steps [sb, sb+7)
#pragma unroll
        for (int jp = 0; jp < 3; jp++) {
          const int s = sb + 2 * jp;
          float o[4];
          gen4(c_sched.key[kb + s], c_sched.key[kb + s + 1], ctrA, ctrB, o);
          s_buf[nb][s][lane]          = o[0];
          s_buf[nb][s][lane + 32]     = o[1];
          s_buf[nb][s + 1][lane]      = o[2];
          s_buf[nb][s + 1][lane + 32] = o[3];
        }
        {
          const int s = sb + 6;
          float o[2];
          gen2(c_sched.key[kb + s], ctrA, ctrB, o);
          s_buf[nb][s][lane]      = o[0];
          s_buf[nb][s][lane + 32] = o[1];
        }
      } else {
        const int sb = wid * 4;                 // steps [sb, sb+4)
#pragma unroll
        for (int jp = 0; jp < 2; jp++) {
          const int s = sb + 2 * jp;
          float o[4];
          gen4(c_sched.key[kb + s], c_sched.key[kb + s + 1], ctrA, ctrB, o);
          s_buf[nb][s][lane]          = o[0];
          s_buf[nb][s][lane + 32]     = o[1];
          s_buf[nb][s + 1][lane]      = o[2];
          s_buf[nb][s + 1][lane + 32] = o[3];
        }
      }
    }

    if (tid < EPB) {
      // consume current chunk: 50 sequential DDIM steps
      float* op = preds + (size_t)(g * CSTEP) * NELEM + base + tid;
#pragma unroll 5
      for (int u = 0; u < CSTEP; u++) {
        const F4 c = c_sched.sc[g * CSTEP + u];   // uniform -> const cache
        const float z  = fmaf(wsil, sil, fmaf(tsc, c.w, cond));
        const float s0 = tanh_fast(z);
        op[(size_t)u * NELEM] = s0;
        sil = fmaf(c.x, s0, fmaf(c.z, s_buf[cb][u][tid], c.y * silT));
      }
    }
    __syncthreads();
  }
}

// =================== launch ===================
extern "C" void kernel_launch(void* const* d_in, const int* in_sizes, int n_in,
                              void* d_out, int out_size) {
  const float* skes    = (const float*)d_in[0];  // (2,3,8,64,44)
  const float* sil_T   = (const float*)d_in[1];  // (16,1,64,44)
  const float* w_skes  = (const float*)d_in[2];  // (3,)
  const float* w_sil   = (const float*)d_in[3];  // ()
  const float* t_scale = (const float*)d_in[4];  // ()
  float* preds = (float*)d_out;                  // (1000,16,1,64,44)

  fused_all<<<NBLK, TPB>>>(skes, sil_T, w_skes, w_sil, t_scale, preds);
}

// round 12
// speedup vs baseline: 1.1980x; 1.0359x over previous
#include <cuda_runtime.h>
#include <stdint.h>

#define NSTEP  1000
#define NELEM  45056     // 16*1*64*44
#define HW     2816      // 64*44
#define EPB    64        // elements per block
#define TPB    256       // warps 0-1 solver(+4 gens), 2-7 producers (7 gens)
#define NBLK   704       // 45056 / 64
#define CSTEP  50        // steps per chunk
#define NCHUNK 20        // 1000 / 50

// =================== compile-time schedule + folded keys ===================
struct alignas(16) F4 { float x, y, z, w; };
struct alignas(16) U4 { unsigned x, y, z, w; };   // {ks0, ks1, ks2, 0}

struct SchedData {
  F4 sc[NSTEP];     // {P, Q, C1, TCO}
  U4 key[NSTEP];    // {ks0, ks1, ks2, 0}
};

constexpr double csqrt(double x) {
  double r = (x > 1.0) ? x : 1.0;
  for (int i = 0; i < 48; i++) r = 0.5 * (r + x / r);
  return r;
}
constexpr unsigned crotl(unsigned v, int r) { return (v << r) | (v >> (32 - r)); }
constexpr void ctf_round(unsigned& x0, unsigned& x1, int r) {
  x0 += x1; x1 = crotl(x1, r); x1 ^= x0;
}
constexpr void cthreefry(unsigned ks0, unsigned ks1, unsigned x0, unsigned x1,
                         unsigned& o0, unsigned& o1) {
  const unsigned ks2 = ks0 ^ ks1 ^ 0x1BD11BDAu;
  x0 += ks0; x1 += ks1;
  ctf_round(x0,x1,13); ctf_round(x0,x1,15); ctf_round(x0,x1,26); ctf_round(x0,x1,6);
  x0 += ks1; x1 += ks2 + 1u;
  ctf_round(x0,x1,17); ctf_round(x0,x1,29); ctf_round(x0,x1,16); ctf_round(x0,x1,24);
  x0 += ks2; x1 += ks0 + 2u;
  ctf_round(x0,x1,13); ctf_round(x0,x1,15); ctf_round(x0,x1,26); ctf_round(x0,x1,6);
  x0 += ks0; x1 += ks1 + 3u;
  ctf_round(x0,x1,17); ctf_round(x0,x1,29); ctf_round(x0,x1,16); ctf_round(x0,x1,24);
  x0 += ks1; x1 += ks2 + 4u;
  ctf_round(x0,x1,13); ctf_round(x0,x1,15); ctf_round(x0,x1,26); ctf_round(x0,x1,6);
  o0 = x0 + ks2;
  o1 = x1 + ks0 + 5u;
}

constexpr SchedData make_sched() {
  SchedData s{};
  double alph[NSTEP + 1] = {};
  alph[0] = 1.0;
  {
    double prod = 1.0;
    const double bstep = (0.02 - 1e-4) / 999.0;
    for (int i = 0; i < NSTEP; i++) {
      double beta = (i == 999) ? 0.02 : (1e-4 + (double)i * bstep);
      prod *= (1.0 - beta);
      alph[i + 1] = prod;
    }
  }
  for (int k = 0; k < NSTEP; k++) {
    const int idx = 999 - k;
    const float at  = (float)alph[idx + 1];
    const float atn = (float)alph[idx];            // k==999 -> 1.0
    const float a1  = 1.0f - at / atn;
    const float c1  = 0.1f * (float)csqrt((double)(a1 * (1.0f - atn) / (1.0f - at)));
    float t2 = 1.0f - atn - c1 * c1; if (t2 < 0.0f) t2 = 0.0f;
    const float c2  = (float)csqrt((double)t2);
    const double s1 = csqrt(1.0 - (double)at);
    const double Qd = (double)c2 / s1;                               // coeff of sil_T
    const double Pd = (double)(float)csqrt((double)atn)
                    - Qd * (double)(float)csqrt((double)at);         // coeff of sil_0
    s.sc[k].x = (float)Pd; s.sc[k].y = (float)Qd; s.sc[k].z = c1;
    s.sc[k].w = (float)idx / 1000.0f;
    unsigned k0 = 0, k1 = 0;
    cthreefry(0u, 42u, 0u, (unsigned)idx, k0, k1);   // fold_in(key(42), idx)
    s.key[k].x = k0; s.key[k].y = k1;
    s.key[k].z = k0 ^ k1 ^ 0x1BD11BDAu;
    s.key[k].w = 0u;
  }
  return s;
}

__constant__ SchedData c_sched = make_sched();

// ============ erfinv poly with sqrt(2) pre-folded into coefficients ============
__device__ __forceinline__ float erfinv_sqrt2_times(float u, float w) {
  float p;
  if (w < 5.0f) {
    w -= 2.5f;
    p =             3.97426473e-08f;
    p = fmaf(p, w,  4.85462767e-07f);
    p = fmaf(p, w, -4.98282941e-06f);
    p = fmaf(p, w, -6.21047292e-06f);
    p = fmaf(p, w,  3.09119798e-04f);
    p = fmaf(p, w, -1.77304226e-03f);
    p = fmaf(p, w, -5.90813969e-03f);
    p = fmaf(p, w,  3.48803866e-01f);
    p = fmaf(p, w,  2.12331426e+00f);
  } else {
    w = sqrtf(w) - 3.0f;
    p =            -2.83146474e-04f;
    p = fmaf(p, w,  1.42765667e-04f);
    p = fmaf(p, w,  1.90826894e-03f);
    p = fmaf(p, w, -5.19508745e-03f);
    p = fmaf(p, w,  8.11695397e-03f);
    p = fmaf(p, w, -1.07798600e-02f);
    p = fmaf(p, w,  1.33486509e-02f);
    p = fmaf(p, w,  1.41658103e+00f);
    p = fmaf(p, w,  4.00626600e+00f);
  }
  return p * u;
}

// =================== 2-wide interleaved threefry -> 2 normals ===================
#define R2(RR)                                                 \
  _Pragma("unroll") for (int j = 0; j < 2; j++) {              \
    x0[j] += x1[j];                                            \
    x1[j] = __funnelshift_l(x1[j], x1[j], (RR)) ^ x0[j];       \
  }

__device__ __forceinline__ float2 gen2(U4 kk, uint32_t ctrA, uint32_t ctrB) {
  const uint32_t ks0 = kk.x, ks1 = kk.y, ks2 = kk.z;
  uint32_t x0[2], x1[2];
  x0[0] = ks0; x1[0] = ctrA + ks1;
  x0[1] = ks0; x1[1] = ctrB + ks1;
  R2(13) R2(15) R2(26) R2(6)
#pragma unroll
  for (int j = 0; j < 2; j++) { x0[j] += ks1; x1[j] += ks2 + 1u; }
  R2(17) R2(29) R2(16) R2(24)
#pragma unroll
  for (int j = 0; j < 2; j++) { x0[j] += ks2; x1[j] += ks0 + 2u; }
  R2(13) R2(15) R2(26) R2(6)
#pragma unroll
  for (int j = 0; j < 2; j++) { x0[j] += ks0; x1[j] += ks1 + 3u; }
  R2(17) R2(29) R2(16) R2(24)
#pragma unroll
  for (int j = 0; j < 2; j++) { x0[j] += ks1; x1[j] += ks2 + 4u; }
  R2(13) R2(15) R2(26) R2(6)

  float uu[2], ww[2];
#pragma unroll
  for (int j = 0; j < 2; j++) {
    const uint32_t bits = (x0[j] + ks2) ^ (x1[j] + ks0 + 5u);   // o0 ^ o1
    const float f = __uint_as_float((bits >> 9) | 0x3f800000u) - 1.0f;
    uu[j] = fmaf(f, 2.0f, -0.99999994f);
    ww[j] = -__logf(fmaf(-uu[j], uu[j], 1.0f));
  }
  float2 r;
  r.x = erfinv_sqrt2_times(uu[0], ww[0]);
  r.y = erfinv_sqrt2_times(uu[1], ww[1]);
  return r;
}

__device__ __forceinline__ float tanh_fast(float x) {
  float y;
  asm("tanh.approx.f32 %0, %1;" : "=f"(y) : "f"(x));
  return y;
}

// =================== fused producer/consumer-in-block kernel ===================
// 5 blocks/SM -> 740 slots >= 704 grid: true single wave.
__global__ void __launch_bounds__(TPB, 5) fused_all(
    const float* __restrict__ skes, const float* __restrict__ silT_g,
    const float* __restrict__ w_skes, const float* __restrict__ w_sil_p,
    const float* __restrict__ t_scale_p, float* __restrict__ preds)
{
  __shared__ float s_buf[2][CSTEP][EPB];

  const int tid  = threadIdx.x;
  const int lane = tid & 31;
  const int wid  = tid >> 5;            // 0..7
  const int base = blockIdx.x * EPB;
  // paired-element mapping: this thread produces elements (2*lane, 2*lane+1)
  const uint32_t ctrA = (uint32_t)(base + 2 * lane);
  const uint32_t ctrB = ctrA + 1u;

  // solver-only state (tid < EPB); solver thread t owns element base+t,
  // stored at s_buf[..][..][t]  (producer writes float2 at [2*lane])
  float sil = 0.f, silT = 0.f, cond = 0.f, wsil = 0.f, tsc = 0.f;
  if (tid < EPB) {
    const int i  = base + tid;
    const int ns = i / HW;
    const int r  = i - ns * HW;
    const int n  = ns >> 3, sf = ns & 7;
    const float* bp = skes + (size_t)(n * 24 + sf) * HW + r;   // c stride = 8*HW
    cond = bp[0] * w_skes[0] + bp[8 * HW] * w_skes[1] + bp[16 * HW] * w_skes[2];
    silT = silT_g[i];
    wsil = *w_sil_p;
    tsc  = *t_scale_p;
    sil  = silT;
  }

  // ---- prologue: chunk 0 — warp w covers steps w, w+8, ... ----
  for (int s = wid; s < CSTEP; s += 8) {
    const float2 o = gen2(c_sched.key[s], ctrA, ctrB);
    *(float2*)&s_buf[0][s][2 * lane] = o;
  }
  __syncthreads();

  // ---- main loop: 20 chunks ----
  // quotas per chunk: solver warps 0-1 -> 4 gens each; producers 2-7 -> 7 each
  for (int g = 0; g < NCHUNK; g++) {
    const int cb = g & 1, nb = cb ^ 1;

    if (g < NCHUNK - 1) {
      const int kb = (g + 1) * CSTEP;
      if (wid >= 2) {
        const int sb = 8 + (wid - 2) * 7;       // steps [sb, sb+7)
#pragma unroll
        for (int jp = 0; jp < 7; jp++) {
          const float2 o = gen2(c_sched.key[kb + sb + jp], ctrA, ctrB);
          *(float2*)&s_buf[nb][sb + jp][2 * lane] = o;
        }
      } else {
        const int sb = wid * 4;                 // steps [sb, sb+4)
#pragma unroll
        for (int jp = 0; jp < 4; jp++) {
          const float2 o = gen2(c_sched.key[kb + sb + jp], ctrA, ctrB);
          *(float2*)&s_buf[nb][sb + jp][2 * lane] = o;
        }
      }
    }

    if (tid < EPB) {
      // consume current chunk: 50 sequential DDIM steps
      float* op = preds + (size_t)(g * CSTEP) * NELEM + base + tid;
#pragma unroll 5
      for (int u = 0; u < CSTEP; u++) {
        const F4 c = c_sched.sc[g * CSTEP + u];   // uniform -> const cache
        const float z  = fmaf(wsil, sil, fmaf(tsc, c.w, cond));
        const float s0 = tanh_fast(z);
        op[(size_t)u * NELEM] = s0;
        sil = fmaf(c.x, s0, fmaf(c.z, s_buf[cb][u][tid], c.y * silT));
      }
    }
    __syncthreads();
  }
}

// =================== launch ===================
extern "C" void kernel_launch(void* const* d_in, const int* in_sizes, int n_in,
                              void* d_out, int out_size) {
  const float* skes    = (const float*)d_in[0];  // (2,3,8,64,44)
  const float* sil_T   = (const float*)d_in[1];  // (16,1,64,44)
  const float* w_skes  = (const float*)d_in[2];  // (3,)
  const float* w_sil   = (const float*)d_in[3];  // ()
  const float* t_scale = (const float*)d_in[4];  // ()
  float* preds = (float*)d_out;                  // (1000,16,1,64,44)

  fused_all<<<NBLK, TPB>>>(skes, sil_T, w_skes, w_sil, t_scale, preds);
}

// round 13
// speedup vs baseline: 1.3790x; 1.1511x over previous
#include <cuda_runtime.h>
#include <stdint.h>

#define NSTEP  1000
#define NELEM  45056     // 16*1*64*44
#define HW     2816      // 64*44
#define EPB    64        // elements per block
#define TPB    384       // warps 0-1 solver(+1 gen), 2-11 producers (5/4 gens)
#define NBLK   704       // 45056 / 64
#define CSTEP  50        // steps per chunk
#define NCHUNK 20        // 1000 / 50

// =================== compile-time schedule + folded keys ===================
struct alignas(16) F4 { float x, y, z, w; };
struct alignas(16) U4 { unsigned x, y, z, w; };   // {ks0, ks1, ks2, 0}

struct SchedData {
  F4 sc[NSTEP];     // {P, Q, C1, TCO}
  U4 key[NSTEP];    // {ks0, ks1, ks2, 0}
};

constexpr double csqrt(double x) {
  double r = (x > 1.0) ? x : 1.0;
  for (int i = 0; i < 48; i++) r = 0.5 * (r + x / r);
  return r;
}
constexpr unsigned crotl(unsigned v, int r) { return (v << r) | (v >> (32 - r)); }
constexpr void ctf_round(unsigned& x0, unsigned& x1, int r) {
  x0 += x1; x1 = crotl(x1, r); x1 ^= x0;
}
constexpr void cthreefry(unsigned ks0, unsigned ks1, unsigned x0, unsigned x1,
                         unsigned& o0, unsigned& o1) {
  const unsigned ks2 = ks0 ^ ks1 ^ 0x1BD11BDAu;
  x0 += ks0; x1 += ks1;
  ctf_round(x0,x1,13); ctf_round(x0,x1,15); ctf_round(x0,x1,26); ctf_round(x0,x1,6);
  x0 += ks1; x1 += ks2 + 1u;
  ctf_round(x0,x1,17); ctf_round(x0,x1,29); ctf_round(x0,x1,16); ctf_round(x0,x1,24);
  x0 += ks2; x1 += ks0 + 2u;
  ctf_round(x0,x1,13); ctf_round(x0,x1,15); ctf_round(x0,x1,26); ctf_round(x0,x1,6);
  x0 += ks0; x1 += ks1 + 3u;
  ctf_round(x0,x1,17); ctf_round(x0,x1,29); ctf_round(x0,x1,16); ctf_round(x0,x1,24);
  x0 += ks1; x1 += ks2 + 4u;
  ctf_round(x0,x1,13); ctf_round(x0,x1,15); ctf_round(x0,x1,26); ctf_round(x0,x1,6);
  o0 = x0 + ks2;
  o1 = x1 + ks0 + 5u;
}

constexpr SchedData make_sched() {
  SchedData s{};
  double alph[NSTEP + 1] = {};
  alph[0] = 1.0;
  {
    double prod = 1.0;
    const double bstep = (0.02 - 1e-4) / 999.0;
    for (int i = 0; i < NSTEP; i++) {
      double beta = (i == 999) ? 0.02 : (1e-4 + (double)i * bstep);
      prod *= (1.0 - beta);
      alph[i + 1] = prod;
    }
  }
  for (int k = 0; k < NSTEP; k++) {
    const int idx = 999 - k;
    const float at  = (float)alph[idx + 1];
    const float atn = (float)alph[idx];            // k==999 -> 1.0
    const float a1  = 1.0f - at / atn;
    const float c1  = 0.1f * (float)csqrt((double)(a1 * (1.0f - atn) / (1.0f - at)));
    float t2 = 1.0f - atn - c1 * c1; if (t2 < 0.0f) t2 = 0.0f;
    const float c2  = (float)csqrt((double)t2);
    const double s1 = csqrt(1.0 - (double)at);
    const double Qd = (double)c2 / s1;                               // coeff of sil_T
    const double Pd = (double)(float)csqrt((double)atn)
                    - Qd * (double)(float)csqrt((double)at);         // coeff of sil_0
    s.sc[k].x = (float)Pd; s.sc[k].y = (float)Qd; s.sc[k].z = c1;
    s.sc[k].w = (float)idx / 1000.0f;
    unsigned k0 = 0, k1 = 0;
    cthreefry(0u, 42u, 0u, (unsigned)idx, k0, k1);   // fold_in(key(42), idx)
    s.key[k].x = k0; s.key[k].y = k1;
    s.key[k].z = k0 ^ k1 ^ 0x1BD11BDAu;
    s.key[k].w = 0u;
  }
  return s;
}

__constant__ SchedData c_sched = make_sched();

// ============ erfinv poly with sqrt(2) pre-folded into coefficients ============
__device__ __forceinline__ float erfinv_sqrt2_times(float u, float w) {
  float p;
  if (w < 5.0f) {
    w -= 2.5f;
    p =             3.97426473e-08f;
    p = fmaf(p, w,  4.85462767e-07f);
    p = fmaf(p, w, -4.98282941e-06f);
    p = fmaf(p, w, -6.21047292e-06f);
    p = fmaf(p, w,  3.09119798e-04f);
    p = fmaf(p, w, -1.77304226e-03f);
    p = fmaf(p, w, -5.90813969e-03f);
    p = fmaf(p, w,  3.48803866e-01f);
    p = fmaf(p, w,  2.12331426e+00f);
  } else {
    w = sqrtf(w) - 3.0f;
    p =            -2.83146474e-04f;
    p = fmaf(p, w,  1.42765667e-04f);
    p = fmaf(p, w,  1.90826894e-03f);
    p = fmaf(p, w, -5.19508745e-03f);
    p = fmaf(p, w,  8.11695397e-03f);
    p = fmaf(p, w, -1.07798600e-02f);
    p = fmaf(p, w,  1.33486509e-02f);
    p = fmaf(p, w,  1.41658103e+00f);
    p = fmaf(p, w,  4.00626600e+00f);
  }
  return p * u;
}

// =================== 2-wide interleaved threefry -> 2 normals ===================
#define R2(RR)                                                 \
  _Pragma("unroll") for (int j = 0; j < 2; j++) {              \
    x0[j] += x1[j];                                            \
    x1[j] = __funnelshift_l(x1[j], x1[j], (RR)) ^ x0[j];       \
  }

__device__ __forceinline__ float2 gen2(U4 kk, uint32_t ctrA, uint32_t ctrB) {
  const uint32_t ks0 = kk.x, ks1 = kk.y, ks2 = kk.z;
  uint32_t x0[2], x1[2];
  x0[0] = ks0; x1[0] = ctrA + ks1;
  x0[1] = ks0; x1[1] = ctrB + ks1;
  R2(13) R2(15) R2(26) R2(6)
#pragma unroll
  for (int j = 0; j < 2; j++) { x0[j] += ks1; x1[j] += ks2 + 1u; }
  R2(17) R2(29) R2(16) R2(24)
#pragma unroll
  for (int j = 0; j < 2; j++) { x0[j] += ks2; x1[j] += ks0 + 2u; }
  R2(13) R2(15) R2(26) R2(6)
#pragma unroll
  for (int j = 0; j < 2; j++) { x0[j] += ks0; x1[j] += ks1 + 3u; }
  R2(17) R2(29) R2(16) R2(24)
#pragma unroll
  for (int j = 0; j < 2; j++) { x0[j] += ks1; x1[j] += ks2 + 4u; }
  R2(13) R2(15) R2(26) R2(6)

  float uu[2], ww[2];
#pragma unroll
  for (int j = 0; j < 2; j++) {
    const uint32_t bits = (x0[j] + ks2) ^ (x1[j] + ks0 + 5u);   // o0 ^ o1
    const float f = __uint_as_float((bits >> 9) | 0x3f800000u) - 1.0f;
    uu[j] = fmaf(f, 2.0f, -0.99999994f);
    ww[j] = -__logf(fmaf(-uu[j], uu[j], 1.0f));
  }
  float2 r;
  r.x = erfinv_sqrt2_times(uu[0], ww[0]);
  r.y = erfinv_sqrt2_times(uu[1], ww[1]);
  return r;
}

__device__ __forceinline__ float tanh_fast(float x) {
  float y;
  asm("tanh.approx.f32 %0, %1;" : "=f"(y) : "f"(x));
  return y;
}

// =================== fused producer/consumer-in-block kernel ===================
// 5 blocks/SM (60 warps, 1920 thr, 128KB smem) -> 740 slots >= 704: single wave.
__global__ void __launch_bounds__(TPB, 5) fused_all(
    const float* __restrict__ skes, const float* __restrict__ silT_g,
    const float* __restrict__ w_skes, const float* __restrict__ w_sil_p,
    const float* __restrict__ t_scale_p, float* __restrict__ preds)
{
  __shared__ float s_buf[2][CSTEP][EPB];

  const int tid  = threadIdx.x;
  const int lane = tid & 31;
  const int wid  = tid >> 5;            // 0..11
  const int base = blockIdx.x * EPB;
  // paired-element mapping: this thread produces elements (2*lane, 2*lane+1)
  const uint32_t ctrA = (uint32_t)(base + 2 * lane);
  const uint32_t ctrB = ctrA + 1u;

  // solver-only state (tid < EPB); solver thread t owns element base+t
  float sil = 0.f, silT = 0.f, cond = 0.f, wsil = 0.f, tsc = 0.f;
  if (tid < EPB) {
    const int i  = base + tid;
    const int ns = i / HW;
    const int r  = i - ns * HW;
    const int n  = ns >> 3, sf = ns & 7;
    const float* bp = skes + (size_t)(n * 24 + sf) * HW + r;   // c stride = 8*HW
    cond = bp[0] * w_skes[0] + bp[8 * HW] * w_skes[1] + bp[16 * HW] * w_skes[2];
    silT = silT_g[i];
    wsil = *w_sil_p;
    tsc  = *t_scale_p;
    sil  = silT;
  }

  // ---- prologue: chunk 0 — warp w covers steps w, w+12, ... ----
  for (int s = wid; s < CSTEP; s += 12) {
    const float2 o = gen2(c_sched.key[s], ctrA, ctrB);
    *(float2*)&s_buf[0][s][2 * lane] = o;
  }
  __syncthreads();

  // ---- main loop: 20 chunks ----
  // quotas/chunk: solver warps 0-1 -> 1 gen each (steps 0,1);
  // producers 2-9 -> 5 gens; producers 10-11 -> 4 gens (2 + 8*5 + 2*4 = 50)
  for (int g = 0; g < NCHUNK; g++) {
    const int cb = g & 1, nb = cb ^ 1;

    if (g < NCHUNK - 1) {
      const int kb = (g + 1) * CSTEP;
      if (wid >= 2) {
        const int q = wid - 2;                          // 0..9
        const int sb = (q < 8) ? (2 + q * 5) : (42 + (q - 8) * 4);
        const int ng = (q < 8) ? 5 : 4;
#pragma unroll
        for (int jp = 0; jp < 5; jp++) {
          if (jp < ng) {
            const float2 o = gen2(c_sched.key[kb + sb + jp], ctrA, ctrB);
            *(float2*)&s_buf[nb][sb + jp][2 * lane] = o;
          }
        }
      } else {
        const float2 o = gen2(c_sched.key[kb + wid], ctrA, ctrB);
        *(float2*)&s_buf[nb][wid][2 * lane] = o;
      }
    }

    if (tid < EPB) {
      // consume current chunk: 50 sequential DDIM steps
      float* op = preds + (size_t)(g * CSTEP) * NELEM + base + tid;
#pragma unroll 5
      for (int u = 0; u < CSTEP; u++) {
        const F4 c = c_sched.sc[g * CSTEP + u];   // uniform -> const cache
        const float z  = fmaf(wsil, sil, fmaf(tsc, c.w, cond));
        const float s0 = tanh_fast(z);
        op[(size_t)u * NELEM] = s0;
        sil = fmaf(c.x, s0, fmaf(c.z, s_buf[cb][u][tid], c.y * silT));
      }
    }
    __syncthreads();
  }
}

// =================== launch ===================
extern "C" void kernel_launch(void* const* d_in, const int* in_sizes, int n_in,
                              void* d_out, int out_size) {
  const float* skes    = (const float*)d_in[0];  // (2,3,8,64,44)
  const float* sil_T   = (const float*)d_in[1];  // (16,1,64,44)
  const float* w_skes  = (const float*)d_in[2];  // (3,)
  const float* w_sil   = (const float*)d_in[3];  // ()
  const float* t_scale = (const float*)d_in[4];  // ()
  float* preds = (float*)d_out;                  // (1000,16,1,64,44)

  fused_all<<<NBLK, TPB>>>(skes, sil_T, w_skes, w_sil, t_scale, preds);
}